// round 7
// baseline (speedup 1.0000x reference)
#include <cuda_runtime.h>
#include <cstdint>

#define N_NODES 50000
#define N_EDGES 800000
#define D 128
#define BN_EPS 1e-5f

// ---------------- scratch (no allocations allowed) ----------------
__device__ double g_sum[D];
__device__ double g_sumsq[D];
__device__ float  g_scale[D];
__device__ float  g_bias[D];
__device__ unsigned g_done;
__device__ int g_count[N_NODES];
__device__ int g_off[N_NODES + 1];
__device__ int g_cursor[N_NODES];
__device__ int g_csr[N_EDGES];

// ---------------- K1: zero counters + stats ----------------
__global__ void __launch_bounds__(256) k_zero() {
    int i = blockIdx.x * blockDim.x + threadIdx.x;
    if (i < D) { g_sum[i] = 0.0; g_sumsq[i] = 0.0; }
    if (i == 0) g_done = 0;
    if (i < N_NODES) g_count[i] = 0;
}

// ---------------- K2: dst histogram ----------------
__global__ void __launch_bounds__(256) k_hist(const int* __restrict__ dst) {
    int e = blockIdx.x * blockDim.x + threadIdx.x;
    if (e < N_EDGES) atomicAdd(&g_count[dst[e]], 1);
}

// ---------------- K3: exclusive scan (1 block) ----------------
#define SCAN_THREADS 1024
#define SCAN_ITEMS ((N_NODES + SCAN_THREADS - 1) / SCAN_THREADS)   // 49
__global__ void __launch_bounds__(SCAN_THREADS) k_scan() {
    __shared__ int s_part[SCAN_THREADS];
    int t = threadIdx.x;
    int begin = t * SCAN_ITEMS;
    int end = begin + SCAN_ITEMS; if (end > N_NODES) end = N_NODES;

    int sum = 0;
    for (int i = begin; i < end; i++) sum += g_count[i];
    s_part[t] = sum;
    __syncthreads();
    for (int off = 1; off < SCAN_THREADS; off <<= 1) {
        int v = (t >= off) ? s_part[t - off] : 0;
        __syncthreads();
        s_part[t] += v;
        __syncthreads();
    }
    int run = (t == 0) ? 0 : s_part[t - 1];
    for (int i = begin; i < end; i++) {
        int c = g_count[i];
        g_off[i] = run;
        g_cursor[i] = run;
        run += c;
    }
    if (t == SCAN_THREADS - 1) g_off[N_NODES] = N_EDGES;
}

// ---------------- K4: CSR fill ----------------
__global__ void __launch_bounds__(256) k_fill(
    const int* __restrict__ src, const int* __restrict__ dst)
{
    int e = blockIdx.x * blockDim.x + threadIdx.x;
    if (e >= N_EDGES) return;
    int pos = atomicAdd(&g_cursor[dst[e]], 1);
    g_csr[pos] = src[e];
}

// ---------------- K5: fused gather + combine + stats + finalize ----------------
// warp per dst row; lane owns channels [lane*4, lane*4+4)
#define GATHER_BLOCKS 1184
__global__ void __launch_bounds__(256) k_gather(
    const float* __restrict__ h, const float* __restrict__ norm,
    const float* __restrict__ eps_p,
    const float* __restrict__ gamma, const float* __restrict__ beta,
    float* __restrict__ out)
{
    int lane = threadIdx.x & 31;
    int wid  = threadIdx.x >> 5;
    int gw   = blockIdx.x * 8 + wid;
    int nw   = GATHER_BLOCKS * 8;
    float epsv = 1.0f + eps_p[0];

    float4 lsum = make_float4(0.f, 0.f, 0.f, 0.f);
    float4 lsq  = make_float4(0.f, 0.f, 0.f, 0.f);

    for (int r = gw; r < N_NODES; r += nw) {
        int base = g_off[r];
        int end  = g_off[r + 1];
        float nd = __ldg(norm + r);

        float4 acc = make_float4(0.f, 0.f, 0.f, 0.f);
        for (int i = base; i < end; i++) {
            int s = __ldg(g_csr + i);                       // warp-uniform
            float ws = __ldg(norm + s);                     // warp-uniform
            float4 hv = __ldg((const float4*)(h + (size_t)s * D) + lane);
            acc.x = fmaf(hv.x, ws, acc.x);
            acc.y = fmaf(hv.y, ws, acc.y);
            acc.z = fmaf(hv.z, ws, acc.z);
            acc.w = fmaf(hv.w, ws, acc.w);
        }

        float4 hs = __ldg((const float4*)(h + (size_t)r * D) + lane);
        float a = epsv * nd * nd;
        float4 v;
        v.x = fmaf(hs.x, a, acc.x * nd);
        v.y = fmaf(hs.y, a, acc.y * nd);
        v.z = fmaf(hs.z, a, acc.z * nd);
        v.w = fmaf(hs.w, a, acc.w * nd);
        ((float4*)(out + (size_t)r * D))[lane] = v;

        lsum.x += v.x; lsum.y += v.y; lsum.z += v.z; lsum.w += v.w;
        lsq.x  = fmaf(v.x, v.x, lsq.x);
        lsq.y  = fmaf(v.y, v.y, lsq.y);
        lsq.z  = fmaf(v.z, v.z, lsq.z);
        lsq.w  = fmaf(v.w, v.w, lsq.w);
    }

    // block-level stats reduction: 8 warps x 128 channels
    __shared__ float s_sum[8][D];
    __shared__ float s_sq[8][D];
    int c0 = lane * 4;
    s_sum[wid][c0 + 0] = lsum.x; s_sum[wid][c0 + 1] = lsum.y;
    s_sum[wid][c0 + 2] = lsum.z; s_sum[wid][c0 + 3] = lsum.w;
    s_sq[wid][c0 + 0]  = lsq.x;  s_sq[wid][c0 + 1]  = lsq.y;
    s_sq[wid][c0 + 2]  = lsq.z;  s_sq[wid][c0 + 3]  = lsq.w;
    __syncthreads();

    int c = threadIdx.x;
    if (c < D) {
        float ts = 0.f, tq = 0.f;
#pragma unroll
        for (int w2 = 0; w2 < 8; w2++) { ts += s_sum[w2][c]; tq += s_sq[w2][c]; }
        atomicAdd(&g_sum[c],   (double)ts);
        atomicAdd(&g_sumsq[c], (double)tq);
    }

    // last block finalizes scale/bias
    __threadfence();
    __syncthreads();
    __shared__ int s_last;
    if (threadIdx.x == 0)
        s_last = (atomicAdd(&g_done, 1u) == (unsigned)(GATHER_BLOCKS - 1));
    __syncthreads();
    if (s_last && c < D) {
        double su  = __ldcg(&g_sum[c]);
        double ssq = __ldcg(&g_sumsq[c]);
        double mu  = su / (double)N_NODES;
        double var = ssq / (double)N_NODES - mu * mu;
        double rstd = 1.0 / sqrt(var + (double)BN_EPS);
        float sc = gamma[c] * (float)rstd;
        g_scale[c] = sc;
        g_bias[c]  = beta[c] - (float)mu * sc;
    }
}

// ---------------- K6: BN apply + ReLU ----------------
__global__ void __launch_bounds__(256) k_bn(float* __restrict__ out)
{
    __shared__ float4 s_scale4[D / 4];
    __shared__ float4 s_bias4[D / 4];

    int tid = threadIdx.x;
    if (tid < D) {
        ((float*)s_scale4)[tid] = g_scale[tid];
        ((float*)s_bias4)[tid]  = g_bias[tid];
    }
    __syncthreads();

    int i4 = blockIdx.x * blockDim.x + tid;
    if (i4 >= (N_NODES * D) / 4) return;
    int c4 = i4 & (D / 4 - 1);
    float4 sc = s_scale4[c4];
    float4 bi = s_bias4[c4];
    float4 x = ((float4*)out)[i4];
    x.x = fmaxf(fmaf(x.x, sc.x, bi.x), 0.f);
    x.y = fmaxf(fmaf(x.y, sc.y, bi.y), 0.f);
    x.z = fmaxf(fmaf(x.z, sc.z, bi.z), 0.f);
    x.w = fmaxf(fmaf(x.w, sc.w, bi.w), 0.f);
    ((float4*)out)[i4] = x;
}

// ---------------- launch ----------------
extern "C" void kernel_launch(void* const* d_in, const int* in_sizes, int n_in,
                              void* d_out, int out_size)
{
    const float* h     = (const float*)d_in[0];
    const float* norm  = (const float*)d_in[1];
    const float* eps   = (const float*)d_in[2];
    const float* gamma = (const float*)d_in[3];
    const float* beta  = (const float*)d_in[4];
    const int*   src   = (const int*)d_in[5];
    const int*   dst   = (const int*)d_in[6];
    float* out = (float*)d_out;

    (void)in_sizes; (void)n_in; (void)out_size;

    k_zero<<<(N_NODES + 255) / 256, 256>>>();
    k_hist<<<(N_EDGES + 255) / 256, 256>>>(dst);
    k_scan<<<1, SCAN_THREADS>>>();
    k_fill<<<(N_EDGES + 255) / 256, 256>>>(src, dst);
    k_gather<<<GATHER_BLOCKS, 256>>>(h, norm, eps, gamma, beta, out);

    const int total4 = (N_NODES * D) / 4;
    k_bn<<<(total4 + 255) / 256, 256>>>(out);
}